// round 2
// baseline (speedup 1.0000x reference)
#include <cuda_runtime.h>

#define NTN 32768
#define CC 128
#define BG 64
#define NNq 512
#define HH 4
#define DHH 32
#define EE 524288

// ---------------- scratch (device globals; no allocation) ----------------
__device__ __align__(16) float g_agg[NTN * CC];
__device__ int g_cnt[NTN];
__device__ __align__(16) float g_h1[NTN * CC];
__device__ __align__(16) float g_h2[NTN * CC];
__device__ __align__(16) float g_q[NTN * CC];
__device__ __align__(16) float g_kk[NTN * CC];
__device__ __align__(16) float g_v[NTN * CC];
__device__ __align__(16) float g_o[NTN * CC];
__device__ __align__(16) float g_t[NTN * 2 * CC];
__device__ __align__(16) float g_f[NTN * CC];
__device__ __align__(16) float g_sum[3][CC];
__device__ __align__(16) float g_sumsq[3][CC];
__device__ __align__(16) float g_scale[3][CC];
__device__ __align__(16) float g_shift[3][CC];

// ---------------- zero scratch that is accumulated into ----------------
__global__ void zero_k() {
    int i = blockIdx.x * blockDim.x + threadIdx.x;
    if (i < NTN * CC / 4) ((float4*)g_agg)[i] = make_float4(0.f, 0.f, 0.f, 0.f);
    if (i < NTN) g_cnt[i] = 0;
    if (i < 3 * CC) {
        ((float*)g_sum)[i] = 0.f;
        ((float*)g_sumsq)[i] = 0.f;
    }
}

// ---------------- edge aggregation: one warp per edge ----------------
__global__ __launch_bounds__(256) void agg_k(const float* __restrict__ x,
                                             const int* __restrict__ ei) {
    int w = (blockIdx.x * blockDim.x + threadIdx.x) >> 5;
    int lane = threadIdx.x & 31;
    if (w >= EE) return;
    int src = ei[w];
    int dst = ei[EE + w];
    float4 v = ((const float4*)(x + (size_t)src * CC))[lane];
    float* a = g_agg + (size_t)dst * CC + lane * 4;
    atomicAdd(a + 0, v.x);
    atomicAdd(a + 1, v.y);
    atomicAdd(a + 2, v.z);
    atomicAdd(a + 3, v.w);
    if (lane == 0) atomicAdd(&g_cnt[dst], 1);
}

// ---------------- generic 128x128 tiled fp32 GEMM, out[m,n] = sum_k A[m,k] B[n,k] ----------------
// MODE 1: A = g_agg/cnt, + bias + x -> g_h1, stats[0]
// MODE 2: A = x,        + bias      -> scatter q/k/v (q scaled by 1/sqrt(DH))
// MODE 3: A = g_o,      + bias + x -> g_h2, stats[1]
// MODE 4: A = u(h1,h2,bn stats),   -> relu(+bias) -> g_t
// MODE 5: A = g_t (K=256), + bias + u -> g_f, stats[2]
template <int MODE, int KDIM>
__global__ __launch_bounds__(256) void gemm_k(const float* __restrict__ Aarg,
                                              const float* __restrict__ Bmat,
                                              const float* __restrict__ bias,
                                              const float* __restrict__ X) {
    __shared__ float As[8][128];
    __shared__ float Bs[8][128];
    const int tid = threadIdx.x;
    const int m0 = blockIdx.x * 128;
    const int n0 = blockIdx.y * 128;
    const int tx = tid & 15;
    const int ty = tid >> 4;
    const int ar = tid >> 1;
    const int ak = (tid & 1) * 4;

    float acc[8][8];
#pragma unroll
    for (int i = 0; i < 8; i++)
#pragma unroll
        for (int j = 0; j < 8; j++) acc[i][j] = 0.f;

    const float* Abase = Aarg;
    float ascale = 1.f;
    if constexpr (MODE == 1) {
        Abase = g_agg;
        int cn = g_cnt[m0 + ar];
        ascale = 1.f / (float)(cn < 1 ? 1 : cn);
    } else if constexpr (MODE == 3) {
        Abase = g_o;
    } else if constexpr (MODE == 5) {
        Abase = g_t;
    }

    for (int kc = 0; kc < KDIM; kc += 8) {
        float4 av;
        if constexpr (MODE == 4) {
            size_t off = (size_t)(m0 + ar) * CC + kc + ak;
            float4 a1 = *(const float4*)(g_h1 + off);
            float4 a2 = *(const float4*)(g_h2 + off);
            int c = kc + ak;
            av.x = a1.x * g_scale[0][c + 0] + a2.x * g_scale[1][c + 0] + g_shift[0][c + 0] + g_shift[1][c + 0];
            av.y = a1.y * g_scale[0][c + 1] + a2.y * g_scale[1][c + 1] + g_shift[0][c + 1] + g_shift[1][c + 1];
            av.z = a1.z * g_scale[0][c + 2] + a2.z * g_scale[1][c + 2] + g_shift[0][c + 2] + g_shift[1][c + 2];
            av.w = a1.w * g_scale[0][c + 3] + a2.w * g_scale[1][c + 3] + g_shift[0][c + 3] + g_shift[1][c + 3];
        } else {
            av = *(const float4*)(Abase + (size_t)(m0 + ar) * KDIM + kc + ak);
            if constexpr (MODE == 1) {
                av.x *= ascale; av.y *= ascale; av.z *= ascale; av.w *= ascale;
            }
        }
        As[ak + 0][ar] = av.x; As[ak + 1][ar] = av.y;
        As[ak + 2][ar] = av.z; As[ak + 3][ar] = av.w;
        float4 bv = *(const float4*)(Bmat + (size_t)(n0 + ar) * KDIM + kc + ak);
        Bs[ak + 0][ar] = bv.x; Bs[ak + 1][ar] = bv.y;
        Bs[ak + 2][ar] = bv.z; Bs[ak + 3][ar] = bv.w;
        __syncthreads();
#pragma unroll
        for (int k = 0; k < 8; k++) {
            float a[8], b[8];
            *(float4*)&a[0] = *(const float4*)&As[k][ty * 8];
            *(float4*)&a[4] = *(const float4*)&As[k][ty * 8 + 4];
            *(float4*)&b[0] = *(const float4*)&Bs[k][tx * 8];
            *(float4*)&b[4] = *(const float4*)&Bs[k][tx * 8 + 4];
#pragma unroll
            for (int i = 0; i < 8; i++)
#pragma unroll
                for (int j = 0; j < 8; j++) acc[i][j] = fmaf(a[i], b[j], acc[i][j]);
        }
        __syncthreads();
    }

    float4 bi0 = *(const float4*)&bias[n0 + tx * 8];
    float4 bi1 = *(const float4*)&bias[n0 + tx * 8 + 4];

    if constexpr (MODE == 2) {
        int nb = n0 + tx * 8;
        int which = nb >> 7;
        int h = (nb & 127) >> 5;
        int d0 = nb & 31;
        float* dstBuf = which == 0 ? g_q : (which == 1 ? g_kk : g_v);
        float qs = which == 0 ? 0.17677669529663687f : 1.f;
#pragma unroll
        for (int i = 0; i < 8; i++) {
            int m = m0 + ty * 8 + i;
            int b = m >> 9, nn = m & 511;
            float* p = dstBuf + ((((size_t)b * HH + h) * NNq + nn) * DHH + d0);
            float4 v0 = make_float4((acc[i][0] + bi0.x) * qs, (acc[i][1] + bi0.y) * qs,
                                    (acc[i][2] + bi0.z) * qs, (acc[i][3] + bi0.w) * qs);
            float4 v1 = make_float4((acc[i][4] + bi1.x) * qs, (acc[i][5] + bi1.y) * qs,
                                    (acc[i][6] + bi1.z) * qs, (acc[i][7] + bi1.w) * qs);
            *(float4*)p = v0;
            *(float4*)(p + 4) = v1;
        }
    } else if constexpr (MODE == 4) {
#pragma unroll
        for (int i = 0; i < 8; i++) {
            int m = m0 + ty * 8 + i;
            float* p = g_t + (size_t)m * (2 * CC) + n0 + tx * 8;
            float4 v0 = make_float4(fmaxf(acc[i][0] + bi0.x, 0.f), fmaxf(acc[i][1] + bi0.y, 0.f),
                                    fmaxf(acc[i][2] + bi0.z, 0.f), fmaxf(acc[i][3] + bi0.w, 0.f));
            float4 v1 = make_float4(fmaxf(acc[i][4] + bi1.x, 0.f), fmaxf(acc[i][5] + bi1.y, 0.f),
                                    fmaxf(acc[i][6] + bi1.z, 0.f), fmaxf(acc[i][7] + bi1.w, 0.f));
            *(float4*)p = v0;
            *(float4*)(p + 4) = v1;
        }
    } else {
        constexpr int S = (MODE == 1) ? 0 : ((MODE == 3) ? 1 : 2);
        float* Out = (MODE == 1) ? g_h1 : ((MODE == 3) ? g_h2 : g_f);
        float cA[8], cB[8], cS[8];
        if constexpr (MODE == 5) {
#pragma unroll
            for (int j = 0; j < 8; j++) {
                int c = tx * 8 + j;
                cA[j] = g_scale[0][c];
                cB[j] = g_scale[1][c];
                cS[j] = g_shift[0][c] + g_shift[1][c];
            }
        }
        float csum[8], csq[8];
#pragma unroll
        for (int j = 0; j < 8; j++) { csum[j] = 0.f; csq[j] = 0.f; }
        float bi[8] = {bi0.x, bi0.y, bi0.z, bi0.w, bi1.x, bi1.y, bi1.z, bi1.w};
#pragma unroll
        for (int i = 0; i < 8; i++) {
            int m = m0 + ty * 8 + i;
            size_t off = (size_t)m * CC + tx * 8;
            float extra[8];
            if constexpr (MODE == 5) {
                float4 h1a = *(const float4*)(g_h1 + off);
                float4 h1b = *(const float4*)(g_h1 + off + 4);
                float4 h2a = *(const float4*)(g_h2 + off);
                float4 h2b = *(const float4*)(g_h2 + off + 4);
                float h1v[8] = {h1a.x, h1a.y, h1a.z, h1a.w, h1b.x, h1b.y, h1b.z, h1b.w};
                float h2v[8] = {h2a.x, h2a.y, h2a.z, h2a.w, h2b.x, h2b.y, h2b.z, h2b.w};
#pragma unroll
                for (int j = 0; j < 8; j++) extra[j] = h1v[j] * cA[j] + h2v[j] * cB[j] + cS[j];
            } else {
                float4 xa = *(const float4*)(X + off);
                float4 xb = *(const float4*)(X + off + 4);
                extra[0] = xa.x; extra[1] = xa.y; extra[2] = xa.z; extra[3] = xa.w;
                extra[4] = xb.x; extra[5] = xb.y; extra[6] = xb.z; extra[7] = xb.w;
            }
            float v[8];
#pragma unroll
            for (int j = 0; j < 8; j++) {
                v[j] = acc[i][j] + bi[j] + extra[j];
                csum[j] += v[j];
                csq[j] += v[j] * v[j];
            }
            *(float4*)(Out + off) = make_float4(v[0], v[1], v[2], v[3]);
            *(float4*)(Out + off + 4) = make_float4(v[4], v[5], v[6], v[7]);
        }
        __syncthreads();
        float* ssum = &As[0][0];
        float* ssq = &Bs[0][0];
        if (tid < 128) { ssum[tid] = 0.f; ssq[tid] = 0.f; }
        __syncthreads();
#pragma unroll
        for (int j = 0; j < 8; j++) {
            atomicAdd(&ssum[tx * 8 + j], csum[j]);
            atomicAdd(&ssq[tx * 8 + j], csq[j]);
        }
        __syncthreads();
        if (tid < 128) {
            atomicAdd(&g_sum[S][tid], ssum[tid]);
            atomicAdd(&g_sumsq[S][tid], ssq[tid]);
        }
    }
}

// ---------------- BN stats finalize ----------------
__global__ void stats_k(int S, const float* __restrict__ g, const float* __restrict__ b) {
    int c = threadIdx.x;
    float mean = g_sum[S][c] * (1.f / NTN);
    float var = g_sumsq[S][c] * (1.f / NTN) - mean * mean;
    float sc = g[c] * rsqrtf(var + 1e-5f);
    g_scale[S][c] = sc;
    g_shift[S][c] = fmaf(-mean, sc, b[c]);
}

// ---------------- fused attention: one block per (b,h), tiled K/V in static smem ----------------
#define KTILE 128
__global__ __launch_bounds__(512) void attn_k() {
    __shared__ float Ks[KTILE * DHH];
    __shared__ float Vs[KTILE * DHH];
    int bh = blockIdx.x;
    int b = bh >> 2, h = bh & 3;
    const float4* kg = (const float4*)(g_kk + (size_t)bh * NNq * DHH);
    const float4* vg = (const float4*)(g_v + (size_t)bh * NNq * DHH);
    int n = threadIdx.x;
    const float4* q4 = (const float4*)(g_q + ((size_t)bh * NNq + n) * DHH);
    float q[32];
#pragma unroll
    for (int d = 0; d < 8; d++) {
        float4 t = q4[d];
        q[d * 4 + 0] = t.x; q[d * 4 + 1] = t.y; q[d * 4 + 2] = t.z; q[d * 4 + 3] = t.w;
    }
    float mx = -1e30f, l = 0.f;
    float acc[32];
#pragma unroll
    for (int d = 0; d < 32; d++) acc[d] = 0.f;
    const float4* K4 = (const float4*)Ks;
    const float4* V4 = (const float4*)Vs;

    for (int t0 = 0; t0 < NNq; t0 += KTILE) {
        __syncthreads();  // previous tile fully consumed
        // cooperative load of this K/V tile: KTILE*DHH/4 = 1024 float4 per buffer, 512 threads
#pragma unroll
        for (int r = 0; r < KTILE * DHH / 4 / 512; r++) {
            int i = r * 512 + threadIdx.x;
            ((float4*)Ks)[i] = kg[t0 * DHH / 4 + i];
            ((float4*)Vs)[i] = vg[t0 * DHH / 4 + i];
        }
        __syncthreads();

        for (int j0 = 0; j0 < KTILE; j0 += 16) {
            float s[16];
#pragma unroll
            for (int jj = 0; jj < 16; jj++) {
                float dot = 0.f;
#pragma unroll
                for (int dq = 0; dq < 8; dq++) {
                    float4 kv = K4[(j0 + jj) * 8 + dq];
                    dot += q[dq * 4 + 0] * kv.x + q[dq * 4 + 1] * kv.y +
                           q[dq * 4 + 2] * kv.z + q[dq * 4 + 3] * kv.w;
                }
                s[jj] = dot;
            }
            float mc = mx;
#pragma unroll
            for (int jj = 0; jj < 16; jj++) mc = fmaxf(mc, s[jj]);
            float scale = __expf(mx - mc);
            mx = mc;
            l *= scale;
#pragma unroll
            for (int d = 0; d < 32; d++) acc[d] *= scale;
#pragma unroll
            for (int jj = 0; jj < 16; jj++) {
                float p = __expf(s[jj] - mx);
                l += p;
#pragma unroll
                for (int dq = 0; dq < 8; dq++) {
                    float4 vv = V4[(j0 + jj) * 8 + dq];
                    acc[dq * 4 + 0] = fmaf(p, vv.x, acc[dq * 4 + 0]);
                    acc[dq * 4 + 1] = fmaf(p, vv.y, acc[dq * 4 + 1]);
                    acc[dq * 4 + 2] = fmaf(p, vv.z, acc[dq * 4 + 2]);
                    acc[dq * 4 + 3] = fmaf(p, vv.w, acc[dq * 4 + 3]);
                }
            }
        }
    }
    float inv = 1.f / l;
    float* orow = g_o + ((size_t)(b * NNq + n)) * CC + h * DHH;
#pragma unroll
    for (int dq = 0; dq < 8; dq++) {
        ((float4*)orow)[dq] = make_float4(acc[dq * 4 + 0] * inv, acc[dq * 4 + 1] * inv,
                                          acc[dq * 4 + 2] * inv, acc[dq * 4 + 3] * inv);
    }
}

// ---------------- final BN3 ----------------
__global__ void bn3_k(float* __restrict__ out) {
    int i = blockIdx.x * blockDim.x + threadIdx.x;
    if (i >= NTN * CC / 4) return;
    int c = (i * 4) & 127;
    float4 f = ((const float4*)g_f)[i];
    float4 sc = *(const float4*)&g_scale[2][c];
    float4 sh = *(const float4*)&g_shift[2][c];
    ((float4*)out)[i] = make_float4(f.x * sc.x + sh.x, f.y * sc.y + sh.y,
                                    f.z * sc.z + sh.z, f.w * sc.w + sh.w);
}

extern "C" void kernel_launch(void* const* d_in, const int* in_sizes, int n_in,
                              void* d_out, int out_size) {
    const float* x = (const float*)d_in[0];
    const int* ei = (const int*)d_in[1];
    const float* Wc = (const float*)d_in[2];
    const float* bc = (const float*)d_in[3];
    const float* ipw = (const float*)d_in[4];
    const float* ipb = (const float*)d_in[5];
    const float* opw = (const float*)d_in[6];
    const float* opb = (const float*)d_in[7];
    const float* gn1 = (const float*)d_in[8];
    const float* bn1 = (const float*)d_in[9];
    const float* gn2 = (const float*)d_in[10];
    const float* bn2 = (const float*)d_in[11];
    const float* gn3 = (const float*)d_in[12];
    const float* bn3 = (const float*)d_in[13];
    const float* Wm1 = (const float*)d_in[14];
    const float* bm1 = (const float*)d_in[15];
    const float* Wm2 = (const float*)d_in[16];
    const float* bm2 = (const float*)d_in[17];
    float* out = (float*)d_out;

    zero_k<<<4096, 256>>>();
    agg_k<<<EE * 32 / 256, 256>>>(x, ei);

    // local branch: h1 = (agg/cnt) @ Wc^T + bc + x, with BN1 stats
    gemm_k<1, 128><<<dim3(NTN / 128, 1), 256>>>(nullptr, Wc, bc, x);
    stats_k<<<1, 128>>>(0, gn1, bn1);

    // global branch: qkv projection -> q/k/v in [B*H, N, DH] layout
    gemm_k<2, 128><<<dim3(NTN / 128, 3), 256>>>(x, ipw, ipb, nullptr);

    attn_k<<<BG * HH, NNq>>>();

    // h2 = o @ out_proj^T + b + x, with BN2 stats
    gemm_k<3, 128><<<dim3(NTN / 128, 1), 256>>>(nullptr, opw, opb, x);
    stats_k<<<1, 128>>>(1, gn2, bn2);

    // MLP: t = relu(u @ Wm1^T + bm1); f = u + t @ Wm2^T + bm2, with BN3 stats
    gemm_k<4, 128><<<dim3(NTN / 128, 2), 256>>>(nullptr, Wm1, bm1, nullptr);
    gemm_k<5, 256><<<dim3(NTN / 128, 1), 256>>>(nullptr, Wm2, bm2, nullptr);
    stats_k<<<1, 128>>>(2, gn3, bn3);

    bn3_k<<<NTN * CC / 4 / 256, 256>>>(out);
}

// round 3
// speedup vs baseline: 1.1662x; 1.1662x over previous
#include <cuda_runtime.h>

#define NTN 32768
#define CC 128
#define BG 64
#define NNq 512
#define HH 4
#define DHH 32
#define EE 524288

// ---------------- scratch (device globals; no allocation) ----------------
__device__ __align__(16) float g_agg[NTN * CC];
__device__ int g_cnt[NTN];
__device__ __align__(16) float g_h1[NTN * CC];
__device__ __align__(16) float g_h2[NTN * CC];
__device__ __align__(16) float g_q[NTN * CC];
__device__ __align__(16) float g_kk[NTN * CC];
__device__ __align__(16) float g_v[NTN * CC];
__device__ __align__(16) float g_o[NTN * CC];
__device__ __align__(16) float g_t[NTN * 2 * CC];
__device__ __align__(16) float g_f[NTN * CC];
__device__ __align__(16) float g_sum[3][CC];
__device__ __align__(16) float g_sumsq[3][CC];
__device__ __align__(16) float g_scale[3][CC];
__device__ __align__(16) float g_shift[3][CC];

// ---------------- packed fp32x2 helpers (sm_103a FFMA2 path) ----------------
__device__ __forceinline__ void ffma2(float2& d, const float2 a, const float2 b) {
    asm("fma.rn.f32x2 %0, %1, %2, %0;"
        : "+l"(reinterpret_cast<unsigned long long&>(d))
        : "l"(reinterpret_cast<const unsigned long long&>(a)),
          "l"(reinterpret_cast<const unsigned long long&>(b)));
}
__device__ __forceinline__ void fmul2(float2& d, const float2 a) {
    asm("mul.rn.f32x2 %0, %0, %1;"
        : "+l"(reinterpret_cast<unsigned long long&>(d))
        : "l"(reinterpret_cast<const unsigned long long&>(a)));
}

// ---------------- zero scratch that is accumulated into ----------------
__global__ void zero_k() {
    int i = blockIdx.x * blockDim.x + threadIdx.x;
    if (i < NTN * CC / 4) ((float4*)g_agg)[i] = make_float4(0.f, 0.f, 0.f, 0.f);
    if (i < NTN) g_cnt[i] = 0;
    if (i < 3 * CC) {
        ((float*)g_sum)[i] = 0.f;
        ((float*)g_sumsq)[i] = 0.f;
    }
}

// ---------------- edge aggregation: one warp per edge, vectorized RED ----------------
__global__ __launch_bounds__(256) void agg_k(const float* __restrict__ x,
                                             const int* __restrict__ ei) {
    int w = (blockIdx.x * blockDim.x + threadIdx.x) >> 5;
    int lane = threadIdx.x & 31;
    if (w >= EE) return;
    int src = ei[w];
    int dst = ei[EE + w];
    float4 v = ((const float4*)(x + (size_t)src * CC))[lane];
    float* a = g_agg + (size_t)dst * CC + lane * 4;
    asm volatile("red.global.add.v4.f32 [%0], {%1, %2, %3, %4};"
                 :: "l"(a), "f"(v.x), "f"(v.y), "f"(v.z), "f"(v.w)
                 : "memory");
    if (lane == 0) atomicAdd(&g_cnt[dst], 1);
}

// ---------------- generic 128x128 tiled fp32 GEMM, out[m,n] = sum_k A[m,k] B[n,k] ----------------
// MODE 1: A = g_agg/cnt, + bias + x -> g_h1, stats[0]
// MODE 2: A = x,        + bias      -> scatter q/k/v (q scaled by 1/sqrt(DH))
// MODE 3: A = g_o,      + bias + x -> g_h2, stats[1]
// MODE 4: A = u(h1,h2,bn stats),   -> relu(+bias) -> g_t
// MODE 5: A = g_t (K=256), + bias + u -> g_f, stats[2]
#define ACC(i, j) (reinterpret_cast<float*>(acc2[i])[j])
template <int MODE, int KDIM>
__global__ __launch_bounds__(256) void gemm_k(const float* __restrict__ Aarg,
                                              const float* __restrict__ Bmat,
                                              const float* __restrict__ bias,
                                              const float* __restrict__ X) {
    __shared__ float As[8][128];
    __shared__ float Bs[8][128];
    const int tid = threadIdx.x;
    const int m0 = blockIdx.x * 128;
    const int n0 = blockIdx.y * 128;
    const int tx = tid & 15;
    const int ty = tid >> 4;
    const int ar = tid >> 1;
    const int ak = (tid & 1) * 4;

    float2 acc2[8][4];
#pragma unroll
    for (int i = 0; i < 8; i++)
#pragma unroll
        for (int j = 0; j < 4; j++) acc2[i][j] = make_float2(0.f, 0.f);

    const float* Abase = Aarg;
    float ascale = 1.f;
    if constexpr (MODE == 1) {
        Abase = g_agg;
        int cn = g_cnt[m0 + ar];
        ascale = 1.f / (float)(cn < 1 ? 1 : cn);
    } else if constexpr (MODE == 3) {
        Abase = g_o;
    } else if constexpr (MODE == 5) {
        Abase = g_t;
    }

    for (int kc = 0; kc < KDIM; kc += 8) {
        float4 av;
        if constexpr (MODE == 4) {
            size_t off = (size_t)(m0 + ar) * CC + kc + ak;
            float4 a1 = *(const float4*)(g_h1 + off);
            float4 a2 = *(const float4*)(g_h2 + off);
            int c = kc + ak;
            av.x = a1.x * g_scale[0][c + 0] + a2.x * g_scale[1][c + 0] + g_shift[0][c + 0] + g_shift[1][c + 0];
            av.y = a1.y * g_scale[0][c + 1] + a2.y * g_scale[1][c + 1] + g_shift[0][c + 1] + g_shift[1][c + 1];
            av.z = a1.z * g_scale[0][c + 2] + a2.z * g_scale[1][c + 2] + g_shift[0][c + 2] + g_shift[1][c + 2];
            av.w = a1.w * g_scale[0][c + 3] + a2.w * g_scale[1][c + 3] + g_shift[0][c + 3] + g_shift[1][c + 3];
        } else {
            av = *(const float4*)(Abase + (size_t)(m0 + ar) * KDIM + kc + ak);
            if constexpr (MODE == 1) {
                av.x *= ascale; av.y *= ascale; av.z *= ascale; av.w *= ascale;
            }
        }
        As[ak + 0][ar] = av.x; As[ak + 1][ar] = av.y;
        As[ak + 2][ar] = av.z; As[ak + 3][ar] = av.w;
        float4 bv = *(const float4*)(Bmat + (size_t)(n0 + ar) * KDIM + kc + ak);
        Bs[ak + 0][ar] = bv.x; Bs[ak + 1][ar] = bv.y;
        Bs[ak + 2][ar] = bv.z; Bs[ak + 3][ar] = bv.w;
        __syncthreads();
#pragma unroll
        for (int k = 0; k < 8; k++) {
            float4 a0 = *(const float4*)&As[k][ty * 8];
            float4 a1 = *(const float4*)&As[k][ty * 8 + 4];
            float4 b0 = *(const float4*)&Bs[k][tx * 8];
            float4 b1 = *(const float4*)&Bs[k][tx * 8 + 4];
            float avv[8] = {a0.x, a0.y, a0.z, a0.w, a1.x, a1.y, a1.z, a1.w};
            float2 bb[4] = {make_float2(b0.x, b0.y), make_float2(b0.z, b0.w),
                            make_float2(b1.x, b1.y), make_float2(b1.z, b1.w)};
#pragma unroll
            for (int i = 0; i < 8; i++) {
                float2 aa = make_float2(avv[i], avv[i]);
#pragma unroll
                for (int jp = 0; jp < 4; jp++) ffma2(acc2[i][jp], aa, bb[jp]);
            }
        }
        __syncthreads();
    }

    float4 bi0 = *(const float4*)&bias[n0 + tx * 8];
    float4 bi1 = *(const float4*)&bias[n0 + tx * 8 + 4];

    if constexpr (MODE == 2) {
        int nb = n0 + tx * 8;
        int which = nb >> 7;
        int h = (nb & 127) >> 5;
        int d0 = nb & 31;
        float* dstBuf = which == 0 ? g_q : (which == 1 ? g_kk : g_v);
        float qs = which == 0 ? 0.17677669529663687f : 1.f;
#pragma unroll
        for (int i = 0; i < 8; i++) {
            int m = m0 + ty * 8 + i;
            int b = m >> 9, nn = m & 511;
            float* p = dstBuf + ((((size_t)b * HH + h) * NNq + nn) * DHH + d0);
            float4 v0 = make_float4((ACC(i, 0) + bi0.x) * qs, (ACC(i, 1) + bi0.y) * qs,
                                    (ACC(i, 2) + bi0.z) * qs, (ACC(i, 3) + bi0.w) * qs);
            float4 v1 = make_float4((ACC(i, 4) + bi1.x) * qs, (ACC(i, 5) + bi1.y) * qs,
                                    (ACC(i, 6) + bi1.z) * qs, (ACC(i, 7) + bi1.w) * qs);
            *(float4*)p = v0;
            *(float4*)(p + 4) = v1;
        }
    } else if constexpr (MODE == 4) {
#pragma unroll
        for (int i = 0; i < 8; i++) {
            int m = m0 + ty * 8 + i;
            float* p = g_t + (size_t)m * (2 * CC) + n0 + tx * 8;
            float4 v0 = make_float4(fmaxf(ACC(i, 0) + bi0.x, 0.f), fmaxf(ACC(i, 1) + bi0.y, 0.f),
                                    fmaxf(ACC(i, 2) + bi0.z, 0.f), fmaxf(ACC(i, 3) + bi0.w, 0.f));
            float4 v1 = make_float4(fmaxf(ACC(i, 4) + bi1.x, 0.f), fmaxf(ACC(i, 5) + bi1.y, 0.f),
                                    fmaxf(ACC(i, 6) + bi1.z, 0.f), fmaxf(ACC(i, 7) + bi1.w, 0.f));
            *(float4*)p = v0;
            *(float4*)(p + 4) = v1;
        }
    } else {
        constexpr int S = (MODE == 1) ? 0 : ((MODE == 3) ? 1 : 2);
        float* Out = (MODE == 1) ? g_h1 : ((MODE == 3) ? g_h2 : g_f);
        float cA[8], cB[8], cS[8];
        if constexpr (MODE == 5) {
#pragma unroll
            for (int j = 0; j < 8; j++) {
                int c = tx * 8 + j;
                cA[j] = g_scale[0][c];
                cB[j] = g_scale[1][c];
                cS[j] = g_shift[0][c] + g_shift[1][c];
            }
        }
        float csum[8], csq[8];
#pragma unroll
        for (int j = 0; j < 8; j++) { csum[j] = 0.f; csq[j] = 0.f; }
        float bi[8] = {bi0.x, bi0.y, bi0.z, bi0.w, bi1.x, bi1.y, bi1.z, bi1.w};
#pragma unroll
        for (int i = 0; i < 8; i++) {
            int m = m0 + ty * 8 + i;
            size_t off = (size_t)m * CC + tx * 8;
            float extra[8];
            if constexpr (MODE == 5) {
                float4 h1a = *(const float4*)(g_h1 + off);
                float4 h1b = *(const float4*)(g_h1 + off + 4);
                float4 h2a = *(const float4*)(g_h2 + off);
                float4 h2b = *(const float4*)(g_h2 + off + 4);
                float h1v[8] = {h1a.x, h1a.y, h1a.z, h1a.w, h1b.x, h1b.y, h1b.z, h1b.w};
                float h2v[8] = {h2a.x, h2a.y, h2a.z, h2a.w, h2b.x, h2b.y, h2b.z, h2b.w};
#pragma unroll
                for (int j = 0; j < 8; j++) extra[j] = h1v[j] * cA[j] + h2v[j] * cB[j] + cS[j];
            } else {
                float4 xa = *(const float4*)(X + off);
                float4 xb = *(const float4*)(X + off + 4);
                extra[0] = xa.x; extra[1] = xa.y; extra[2] = xa.z; extra[3] = xa.w;
                extra[4] = xb.x; extra[5] = xb.y; extra[6] = xb.z; extra[7] = xb.w;
            }
            float v[8];
#pragma unroll
            for (int j = 0; j < 8; j++) {
                v[j] = ACC(i, j) + bi[j] + extra[j];
                csum[j] += v[j];
                csq[j] += v[j] * v[j];
            }
            *(float4*)(Out + off) = make_float4(v[0], v[1], v[2], v[3]);
            *(float4*)(Out + off + 4) = make_float4(v[4], v[5], v[6], v[7]);
        }
        __syncthreads();
        float* ssum = &As[0][0];
        float* ssq = &Bs[0][0];
        if (tid < 128) { ssum[tid] = 0.f; ssq[tid] = 0.f; }
        __syncthreads();
#pragma unroll
        for (int j = 0; j < 8; j++) {
            atomicAdd(&ssum[tx * 8 + j], csum[j]);
            atomicAdd(&ssq[tx * 8 + j], csq[j]);
        }
        __syncthreads();
        if (tid < 128) {
            atomicAdd(&g_sum[S][tid], ssum[tid]);
            atomicAdd(&g_sumsq[S][tid], ssq[tid]);
        }
    }
}

// ---------------- BN stats finalize ----------------
__global__ void stats_k(int S, const float* __restrict__ g, const float* __restrict__ b) {
    int c = threadIdx.x;
    float mean = g_sum[S][c] * (1.f / NTN);
    float var = g_sumsq[S][c] * (1.f / NTN) - mean * mean;
    float sc = g[c] * rsqrtf(var + 1e-5f);
    g_scale[S][c] = sc;
    g_shift[S][c] = fmaf(-mean, sc, b[c]);
}

// ---------------- fused attention: one block per (b,h), tiled K/V in static smem ----------------
#define KTILE 128
__global__ __launch_bounds__(512) void attn_k() {
    __shared__ float Ks[KTILE * DHH];
    __shared__ float Vs[KTILE * DHH];
    int bh = blockIdx.x;
    int b = bh >> 2, h = bh & 3;
    const float4* kg = (const float4*)(g_kk + (size_t)bh * NNq * DHH);
    const float4* vg = (const float4*)(g_v + (size_t)bh * NNq * DHH);
    int n = threadIdx.x;
    const float4* q4 = (const float4*)(g_q + ((size_t)bh * NNq + n) * DHH);
    float2 q2[16];
#pragma unroll
    for (int d = 0; d < 8; d++) {
        float4 t = q4[d];
        q2[d * 2 + 0] = make_float2(t.x, t.y);
        q2[d * 2 + 1] = make_float2(t.z, t.w);
    }
    float mx = -1e30f, l = 0.f;
    float2 acc2[16];
#pragma unroll
    for (int d = 0; d < 16; d++) acc2[d] = make_float2(0.f, 0.f);
    const float4* K4 = (const float4*)Ks;
    const float4* V4 = (const float4*)Vs;

    for (int t0 = 0; t0 < NNq; t0 += KTILE) {
        __syncthreads();  // previous tile fully consumed
#pragma unroll
        for (int r = 0; r < KTILE * DHH / 4 / 512; r++) {
            int i = r * 512 + threadIdx.x;
            ((float4*)Ks)[i] = kg[t0 * DHH / 4 + i];
            ((float4*)Vs)[i] = vg[t0 * DHH / 4 + i];
        }
        __syncthreads();

        for (int j0 = 0; j0 < KTILE; j0 += 16) {
            float s[16];
#pragma unroll
            for (int jj = 0; jj < 16; jj++) {
                float2 d2 = make_float2(0.f, 0.f);
#pragma unroll
                for (int dq = 0; dq < 8; dq++) {
                    float4 kv = K4[(j0 + jj) * 8 + dq];
                    ffma2(d2, q2[dq * 2 + 0], make_float2(kv.x, kv.y));
                    ffma2(d2, q2[dq * 2 + 1], make_float2(kv.z, kv.w));
                }
                s[jj] = d2.x + d2.y;
            }
            float mc = mx;
#pragma unroll
            for (int jj = 0; jj < 16; jj++) mc = fmaxf(mc, s[jj]);
            float scale = __expf(mx - mc);
            mx = mc;
            l *= scale;
            float2 sc2 = make_float2(scale, scale);
#pragma unroll
            for (int d = 0; d < 16; d++) fmul2(acc2[d], sc2);
#pragma unroll
            for (int jj = 0; jj < 16; jj++) {
                float p = __expf(s[jj] - mx);
                l += p;
                float2 pp = make_float2(p, p);
#pragma unroll
                for (int dq = 0; dq < 8; dq++) {
                    float4 vv = V4[(j0 + jj) * 8 + dq];
                    ffma2(acc2[dq * 2 + 0], pp, make_float2(vv.x, vv.y));
                    ffma2(acc2[dq * 2 + 1], pp, make_float2(vv.z, vv.w));
                }
            }
        }
    }
    float inv = 1.f / l;
    float* orow = g_o + ((size_t)(b * NNq + n)) * CC + h * DHH;
#pragma unroll
    for (int dq = 0; dq < 8; dq++) {
        ((float4*)orow)[dq] = make_float4(acc2[dq * 2].x * inv, acc2[dq * 2].y * inv,
                                          acc2[dq * 2 + 1].x * inv, acc2[dq * 2 + 1].y * inv);
    }
}

// ---------------- final BN3 ----------------
__global__ void bn3_k(float* __restrict__ out) {
    int i = blockIdx.x * blockDim.x + threadIdx.x;
    if (i >= NTN * CC / 4) return;
    int c = (i * 4) & 127;
    float4 f = ((const float4*)g_f)[i];
    float4 sc = *(const float4*)&g_scale[2][c];
    float4 sh = *(const float4*)&g_shift[2][c];
    ((float4*)out)[i] = make_float4(f.x * sc.x + sh.x, f.y * sc.y + sh.y,
                                    f.z * sc.z + sh.z, f.w * sc.w + sh.w);
}

extern "C" void kernel_launch(void* const* d_in, const int* in_sizes, int n_in,
                              void* d_out, int out_size) {
    const float* x = (const float*)d_in[0];
    const int* ei = (const int*)d_in[1];
    const float* Wc = (const float*)d_in[2];
    const float* bc = (const float*)d_in[3];
    const float* ipw = (const float*)d_in[4];
    const float* ipb = (const float*)d_in[5];
    const float* opw = (const float*)d_in[6];
    const float* opb = (const float*)d_in[7];
    const float* gn1 = (const float*)d_in[8];
    const float* bn1 = (const float*)d_in[9];
    const float* gn2 = (const float*)d_in[10];
    const float* bn2 = (const float*)d_in[11];
    const float* gn3 = (const float*)d_in[12];
    const float* bn3 = (const float*)d_in[13];
    const float* Wm1 = (const float*)d_in[14];
    const float* bm1 = (const float*)d_in[15];
    const float* Wm2 = (const float*)d_in[16];
    const float* bm2 = (const float*)d_in[17];
    float* out = (float*)d_out;

    zero_k<<<4096, 256>>>();
    agg_k<<<EE * 32 / 256, 256>>>(x, ei);

    // local branch: h1 = (agg/cnt) @ Wc^T + bc + x, with BN1 stats
    gemm_k<1, 128><<<dim3(NTN / 128, 1), 256>>>(nullptr, Wc, bc, x);
    stats_k<<<1, 128>>>(0, gn1, bn1);

    // global branch: qkv projection -> q/k/v in [B*H, N, DH] layout
    gemm_k<2, 128><<<dim3(NTN / 128, 3), 256>>>(x, ipw, ipb, nullptr);

    attn_k<<<BG * HH, NNq>>>();

    // h2 = o @ out_proj^T + b + x, with BN2 stats
    gemm_k<3, 128><<<dim3(NTN / 128, 1), 256>>>(nullptr, opw, opb, x);
    stats_k<<<1, 128>>>(1, gn2, bn2);

    // MLP: t = relu(u @ Wm1^T + bm1); f = u + t @ Wm2^T + bm2, with BN3 stats
    gemm_k<4, 128><<<dim3(NTN / 128, 2), 256>>>(nullptr, Wm1, bm1, nullptr);
    gemm_k<5, 256><<<dim3(NTN / 128, 1), 256>>>(nullptr, Wm2, bm2, nullptr);
    stats_k<<<1, 128>>>(2, gn3, bn3);

    bn3_k<<<NTN * CC / 4 / 256, 256>>>(out);
}

// round 6
// speedup vs baseline: 1.3889x; 1.1910x over previous
#include <cuda_runtime.h>
#include <cstdint>

#define NTN 32768
#define CC 128
#define BG 64
#define NNq 512
#define HH 4
#define DHH 32
#define EE 524288

#define LDP 132  // padded smem row stride (floats)
#define SOFF_B (128 * LDP)
#define SMEM_DYN (2 * 128 * LDP * 4)

// ---------------- scratch (device globals; no allocation) ----------------
__device__ __align__(16) float g_agg[NTN * CC];
__device__ int g_cnt[NTN];
__device__ __align__(16) float g_h1[NTN * CC];
__device__ __align__(16) float g_h2[NTN * CC];
__device__ __align__(16) float g_q[NTN * CC];
__device__ __align__(16) float g_kk[NTN * CC];
__device__ __align__(16) float g_v[NTN * CC];
__device__ __align__(16) float g_o[NTN * CC];
__device__ __align__(16) float g_t[NTN * 2 * CC];
__device__ __align__(16) float g_f[NTN * CC];
__device__ __align__(16) float g_sum[3][CC];
__device__ __align__(16) float g_sumsq[3][CC];
__device__ __align__(16) float g_scale[3][CC];
__device__ __align__(16) float g_shift[3][CC];

// ---------------- helpers ----------------
__device__ __forceinline__ void ffma2(float2& d, const float2 a, const float2 b) {
    asm("fma.rn.f32x2 %0, %1, %2, %0;"
        : "+l"(reinterpret_cast<unsigned long long&>(d))
        : "l"(reinterpret_cast<const unsigned long long&>(a)),
          "l"(reinterpret_cast<const unsigned long long&>(b)));
}
__device__ __forceinline__ void fmul2(float2& d, const float2 a) {
    asm("mul.rn.f32x2 %0, %0, %1;"
        : "+l"(reinterpret_cast<unsigned long long&>(d))
        : "l"(reinterpret_cast<const unsigned long long&>(a)));
}
__device__ __forceinline__ uint32_t f2tf32(float f) {
    uint32_t u;
    asm("cvt.rna.tf32.f32 %0, %1;" : "=r"(u) : "f"(f));
    return u;
}
__device__ __forceinline__ void mma_tf32(float* c, const uint32_t* a, const uint32_t* b) {
    asm volatile(
        "mma.sync.aligned.m16n8k8.row.col.f32.tf32.tf32.f32 "
        "{%0,%1,%2,%3}, {%4,%5,%6,%7}, {%8,%9}, {%0,%1,%2,%3};"
        : "+f"(c[0]), "+f"(c[1]), "+f"(c[2]), "+f"(c[3])
        : "r"(a[0]), "r"(a[1]), "r"(a[2]), "r"(a[3]), "r"(b[0]), "r"(b[1]));
}

// ---------------- zero scratch ----------------
__global__ void zero_k() {
    int i = blockIdx.x * blockDim.x + threadIdx.x;
    if (i < NTN * CC / 4) ((float4*)g_agg)[i] = make_float4(0.f, 0.f, 0.f, 0.f);
    if (i < NTN) g_cnt[i] = 0;
    if (i < 3 * CC) {
        ((float*)g_sum)[i] = 0.f;
        ((float*)g_sumsq)[i] = 0.f;
    }
}

// ---------------- edge aggregation ----------------
__global__ __launch_bounds__(256) void agg_k(const float* __restrict__ x,
                                             const int* __restrict__ ei) {
    int w = (blockIdx.x * blockDim.x + threadIdx.x) >> 5;
    int lane = threadIdx.x & 31;
    if (w >= EE) return;
    int src = ei[w];
    int dst = ei[EE + w];
    float4 v = ((const float4*)(x + (size_t)src * CC))[lane];
    float* a = g_agg + (size_t)dst * CC + lane * 4;
    asm volatile("red.global.add.v4.f32 [%0], {%1, %2, %3, %4};"
                 :: "l"(a), "f"(v.x), "f"(v.y), "f"(v.z), "f"(v.w) : "memory");
    if (lane == 0) atomicAdd(&g_cnt[dst], 1);
}

// ---------------- tf32 mma.sync GEMM: out[m,n] = sum_k A[m,k] B[n,k] ----------------
// MODE 1: A = g_agg/cnt, epi: + bias + x -> g_h1
// MODE 2: A = x, epi: scatter q/k/v (blockIdx.y = which, q scaled)
// MODE 3: A = g_o, epi: + bias + x -> g_h2
// MODE 4: A = bn1(h1)+bn2(h2), epi: relu(+bias) -> g_t (blockIdx.y = n-half)
// MODE 5: A = g_t (K=256), epi: + bias + u -> g_f
template <int MODE>
__global__ __launch_bounds__(256) void tgemm_k(const float* __restrict__ Bmat,
                                               const float* __restrict__ bias,
                                               const float* __restrict__ X) {
    extern __shared__ uint32_t smem[];
    uint32_t* As = smem;
    uint32_t* Bs = smem + SOFF_B;
    constexpr int KDIM = (MODE == 5) ? 256 : 128;
    constexpr int NCH = KDIM / 128;
    const int tid = threadIdx.x;
    const int wid = tid >> 5;
    const int lid = tid & 31;
    const int m0 = blockIdx.x * 128;
    const int n0 = blockIdx.y * 128;

    const int lrow = tid >> 1;            // 0..127
    const int lcol0 = (tid & 1) * 64;     // 0 or 64

    float acc[4][4][4];
#pragma unroll
    for (int i = 0; i < 4; i++)
#pragma unroll
        for (int j = 0; j < 4; j++)
#pragma unroll
            for (int r = 0; r < 4; r++) acc[i][j][r] = 0.f;

    float ascale = 1.f;
    if constexpr (MODE == 1) {
        int cn = g_cnt[m0 + lrow];
        ascale = 1.f / (float)(cn < 1 ? 1 : cn);
    }

    const int rowbase = (wid & 1) * 64;
    const int colbase = (wid >> 1) * 32;

    for (int c = 0; c < NCH; c++) {
        if (c) __syncthreads();
        // ---- stage A row lrow, cols [lcol0, lcol0+64) ----
#pragma unroll 4
        for (int k4 = 0; k4 < 64; k4 += 4) {
            int k = lcol0 + k4;
            float4 v;
            if constexpr (MODE == 4) {
                size_t off = (size_t)(m0 + lrow) * CC + k;
                float4 a1 = *(const float4*)(g_h1 + off);
                float4 a2 = *(const float4*)(g_h2 + off);
                v.x = a1.x * g_scale[0][k + 0] + a2.x * g_scale[1][k + 0] + g_shift[0][k + 0] + g_shift[1][k + 0];
                v.y = a1.y * g_scale[0][k + 1] + a2.y * g_scale[1][k + 1] + g_shift[0][k + 1] + g_shift[1][k + 1];
                v.z = a1.z * g_scale[0][k + 2] + a2.z * g_scale[1][k + 2] + g_shift[0][k + 2] + g_shift[1][k + 2];
                v.w = a1.w * g_scale[0][k + 3] + a2.w * g_scale[1][k + 3] + g_shift[0][k + 3] + g_shift[1][k + 3];
            } else {
                const float* Arow;
                if constexpr (MODE == 1) Arow = g_agg + (size_t)(m0 + lrow) * CC;
                else if constexpr (MODE == 3) Arow = g_o + (size_t)(m0 + lrow) * CC;
                else if constexpr (MODE == 5) Arow = g_t + (size_t)(m0 + lrow) * 256 + c * 128;
                else Arow = X + (size_t)(m0 + lrow) * CC;
                v = *(const float4*)(Arow + k);
                if constexpr (MODE == 1) { v.x *= ascale; v.y *= ascale; v.z *= ascale; v.w *= ascale; }
            }
            *(uint4*)(As + lrow * LDP + k) =
                make_uint4(f2tf32(v.x), f2tf32(v.y), f2tf32(v.z), f2tf32(v.w));
        }
        // ---- stage B row lrow (n index), cols [lcol0, lcol0+64) ----
        const float* Brow = Bmat + (size_t)(n0 + lrow) * KDIM + c * 128;
#pragma unroll 4
        for (int k4 = 0; k4 < 64; k4 += 4) {
            int k = lcol0 + k4;
            float4 v = *(const float4*)(Brow + k);
            *(uint4*)(Bs + lrow * LDP + k) =
                make_uint4(f2tf32(v.x), f2tf32(v.y), f2tf32(v.z), f2tf32(v.w));
        }
        __syncthreads();

        // ---- mma mainloop ----
        const int g4 = lid >> 2, l4 = lid & 3;
#pragma unroll
        for (int k0 = 0; k0 < 128; k0 += 8) {
            uint32_t a[4][4], b[4][2];
#pragma unroll
            for (int im = 0; im < 4; im++) {
                int r0 = rowbase + im * 16 + g4;
                a[im][0] = As[r0 * LDP + k0 + l4];
                a[im][1] = As[(r0 + 8) * LDP + k0 + l4];
                a[im][2] = As[r0 * LDP + k0 + 4 + l4];
                a[im][3] = As[(r0 + 8) * LDP + k0 + 4 + l4];
            }
#pragma unroll
            for (int jn = 0; jn < 4; jn++) {
                int cn0 = colbase + jn * 8 + g4;
                b[jn][0] = Bs[cn0 * LDP + k0 + l4];
                b[jn][1] = Bs[cn0 * LDP + k0 + 4 + l4];
            }
#pragma unroll
            for (int im = 0; im < 4; im++)
#pragma unroll
                for (int jn = 0; jn < 4; jn++) mma_tf32(acc[im][jn], a[im], b[jn]);
        }
    }

    // ---- epilogue ----
    const int g4 = lid >> 2, l4 = lid & 3;
#pragma unroll
    for (int im = 0; im < 4; im++) {
#pragma unroll
        for (int jn = 0; jn < 4; jn++) {
            int r_lo = m0 + rowbase + im * 16 + g4;
            int r_hi = r_lo + 8;
            int cl = colbase + jn * 8 + 2 * l4;  // local col 0..127
            float2 bi = *(const float2*)(bias + n0 + cl);
            float2 v0 = make_float2(acc[im][jn][0] + bi.x, acc[im][jn][1] + bi.y);
            float2 v1 = make_float2(acc[im][jn][2] + bi.x, acc[im][jn][3] + bi.y);

            if constexpr (MODE == 2) {
                int which = blockIdx.y;
                float qs = (which == 0) ? 0.17677669529663687f : 1.f;
                float* dstBuf = which == 0 ? g_q : (which == 1 ? g_kk : g_v);
                int h = cl >> 5, d0 = cl & 31;
                v0.x *= qs; v0.y *= qs; v1.x *= qs; v1.y *= qs;
                {
                    int bb = r_lo >> 9, nn = r_lo & 511;
                    *(float2*)(dstBuf + (((size_t)(bb * HH + h) * NNq + nn) * DHH + d0)) = v0;
                }
                {
                    int bb = r_hi >> 9, nn = r_hi & 511;
                    *(float2*)(dstBuf + (((size_t)(bb * HH + h) * NNq + nn) * DHH + d0)) = v1;
                }
            } else if constexpr (MODE == 4) {
                v0.x = fmaxf(v0.x, 0.f); v0.y = fmaxf(v0.y, 0.f);
                v1.x = fmaxf(v1.x, 0.f); v1.y = fmaxf(v1.y, 0.f);
                *(float2*)(g_t + (size_t)r_lo * 256 + n0 + cl) = v0;
                *(float2*)(g_t + (size_t)r_hi * 256 + n0 + cl) = v1;
            } else if constexpr (MODE == 5) {
                float sa0 = g_scale[0][cl], sa1 = g_scale[0][cl + 1];
                float sb0 = g_scale[1][cl], sb1 = g_scale[1][cl + 1];
                float sh0 = g_shift[0][cl] + g_shift[1][cl];
                float sh1 = g_shift[0][cl + 1] + g_shift[1][cl + 1];
                {
                    float2 h1 = *(const float2*)(g_h1 + (size_t)r_lo * CC + cl);
                    float2 h2 = *(const float2*)(g_h2 + (size_t)r_lo * CC + cl);
                    v0.x += h1.x * sa0 + h2.x * sb0 + sh0;
                    v0.y += h1.y * sa1 + h2.y * sb1 + sh1;
                    *(float2*)(g_f + (size_t)r_lo * CC + cl) = v0;
                }
                {
                    float2 h1 = *(const float2*)(g_h1 + (size_t)r_hi * CC + cl);
                    float2 h2 = *(const float2*)(g_h2 + (size_t)r_hi * CC + cl);
                    v1.x += h1.x * sa0 + h2.x * sb0 + sh0;
                    v1.y += h1.y * sa1 + h2.y * sb1 + sh1;
                    *(float2*)(g_f + (size_t)r_hi * CC + cl) = v1;
                }
            } else {
                float* Out = (MODE == 1) ? g_h1 : g_h2;
                {
                    float2 xx = *(const float2*)(X + (size_t)r_lo * CC + cl);
                    v0.x += xx.x; v0.y += xx.y;
                    *(float2*)(Out + (size_t)r_lo * CC + cl) = v0;
                }
                {
                    float2 xx = *(const float2*)(X + (size_t)r_hi * CC + cl);
                    v1.x += xx.x; v1.y += xx.y;
                    *(float2*)(Out + (size_t)r_hi * CC + cl) = v1;
                }
            }
        }
    }
}

// ---------------- BN column stats (src selected DEVICE-side: no host symbol UB) ----------------
__global__ __launch_bounds__(256) void ssum_k(int S) {
    const float* src = (S == 0) ? g_h1 : ((S == 1) ? g_h2 : g_f);
    int col = threadIdx.x & 127;
    int half = threadIdx.x >> 7;
    size_t r0 = (size_t)blockIdx.x * 128 + half * 64;
    float s = 0.f, q = 0.f;
#pragma unroll 4
    for (int i = 0; i < 64; i++) {
        float v = src[(r0 + i) * CC + col];
        s += v;
        q += v * v;
    }
    atomicAdd(&g_sum[S][col], s);
    atomicAdd(&g_sumsq[S][col], q);
}

// ---------------- BN stats finalize ----------------
__global__ void stats_k(int S, const float* __restrict__ g, const float* __restrict__ b) {
    int c = threadIdx.x;
    float mean = g_sum[S][c] * (1.f / NTN);
    float var = g_sumsq[S][c] * (1.f / NTN) - mean * mean;
    float sc = g[c] * rsqrtf(var + 1e-5f);
    g_scale[S][c] = sc;
    g_shift[S][c] = fmaf(-mean, sc, b[c]);
}

// ---------------- fused attention (f32x2 SIMT) ----------------
#define KTILE 128
__global__ __launch_bounds__(512) void attn_k() {
    __shared__ float Ks[KTILE * DHH];
    __shared__ float Vs[KTILE * DHH];
    int bh = blockIdx.x;
    int b = bh >> 2, h = bh & 3;
    const float4* kg = (const float4*)(g_kk + (size_t)bh * NNq * DHH);
    const float4* vg = (const float4*)(g_v + (size_t)bh * NNq * DHH);
    int n = threadIdx.x;
    const float4* q4 = (const float4*)(g_q + ((size_t)bh * NNq + n) * DHH);
    float2 q2[16];
#pragma unroll
    for (int d = 0; d < 8; d++) {
        float4 t = q4[d];
        q2[d * 2 + 0] = make_float2(t.x, t.y);
        q2[d * 2 + 1] = make_float2(t.z, t.w);
    }
    float mx = -1e30f, l = 0.f;
    float2 acc2[16];
#pragma unroll
    for (int d = 0; d < 16; d++) acc2[d] = make_float2(0.f, 0.f);
    const float4* K4 = (const float4*)Ks;
    const float4* V4 = (const float4*)Vs;

    for (int t0 = 0; t0 < NNq; t0 += KTILE) {
        __syncthreads();
#pragma unroll
        for (int rr = 0; rr < KTILE * DHH / 4 / 512; rr++) {
            int i = rr * 512 + threadIdx.x;
            ((float4*)Ks)[i] = kg[t0 * DHH / 4 + i];
            ((float4*)Vs)[i] = vg[t0 * DHH / 4 + i];
        }
        __syncthreads();

        for (int j0 = 0; j0 < KTILE; j0 += 16) {
            float s[16];
#pragma unroll
            for (int jj = 0; jj < 16; jj++) {
                float2 d2 = make_float2(0.f, 0.f);
#pragma unroll
                for (int dq = 0; dq < 8; dq++) {
                    float4 kv = K4[(j0 + jj) * 8 + dq];
                    ffma2(d2, q2[dq * 2 + 0], make_float2(kv.x, kv.y));
                    ffma2(d2, q2[dq * 2 + 1], make_float2(kv.z, kv.w));
                }
                s[jj] = d2.x + d2.y;
            }
            float mc = mx;
#pragma unroll
            for (int jj = 0; jj < 16; jj++) mc = fmaxf(mc, s[jj]);
            float scale = __expf(mx - mc);
            mx = mc;
            l *= scale;
            float2 sc2 = make_float2(scale, scale);
#pragma unroll
            for (int d = 0; d < 16; d++) fmul2(acc2[d], sc2);
#pragma unroll
            for (int jj = 0; jj < 16; jj++) {
                float p = __expf(s[jj] - mx);
                l += p;
                float2 pp = make_float2(p, p);
#pragma unroll
                for (int dq = 0; dq < 8; dq++) {
                    float4 vv = V4[(j0 + jj) * 8 + dq];
                    ffma2(acc2[dq * 2 + 0], pp, make_float2(vv.x, vv.y));
                    ffma2(acc2[dq * 2 + 1], pp, make_float2(vv.z, vv.w));
                }
            }
        }
    }
    float inv = 1.f / l;
    float* orow = g_o + ((size_t)(b * NNq + n)) * CC + h * DHH;
#pragma unroll
    for (int dq = 0; dq < 8; dq++) {
        ((float4*)orow)[dq] = make_float4(acc2[dq * 2].x * inv, acc2[dq * 2].y * inv,
                                          acc2[dq * 2 + 1].x * inv, acc2[dq * 2 + 1].y * inv);
    }
}

// ---------------- final BN3 ----------------
__global__ void bn3_k(float* __restrict__ out) {
    int i = blockIdx.x * blockDim.x + threadIdx.x;
    if (i >= NTN * CC / 4) return;
    int c = (i * 4) & 127;
    float4 f = ((const float4*)g_f)[i];
    float4 sc = *(const float4*)&g_scale[2][c];
    float4 sh = *(const float4*)&g_shift[2][c];
    ((float4*)out)[i] = make_float4(f.x * sc.x + sh.x, f.y * sc.y + sh.y,
                                    f.z * sc.z + sh.z, f.w * sc.w + sh.w);
}

extern "C" void kernel_launch(void* const* d_in, const int* in_sizes, int n_in,
                              void* d_out, int out_size) {
    const float* x = (const float*)d_in[0];
    const int* ei = (const int*)d_in[1];
    const float* Wc = (const float*)d_in[2];
    const float* bc = (const float*)d_in[3];
    const float* ipw = (const float*)d_in[4];
    const float* ipb = (const float*)d_in[5];
    const float* opw = (const float*)d_in[6];
    const float* opb = (const float*)d_in[7];
    const float* gn1 = (const float*)d_in[8];
    const float* bn1 = (const float*)d_in[9];
    const float* gn2 = (const float*)d_in[10];
    const float* bn2 = (const float*)d_in[11];
    const float* gn3 = (const float*)d_in[12];
    const float* bn3 = (const float*)d_in[13];
    const float* Wm1 = (const float*)d_in[14];
    const float* bm1 = (const float*)d_in[15];
    const float* Wm2 = (const float*)d_in[16];
    const float* bm2 = (const float*)d_in[17];
    float* out = (float*)d_out;

    cudaFuncSetAttribute(tgemm_k<1>, cudaFuncAttributeMaxDynamicSharedMemorySize, SMEM_DYN);
    cudaFuncSetAttribute(tgemm_k<2>, cudaFuncAttributeMaxDynamicSharedMemorySize, SMEM_DYN);
    cudaFuncSetAttribute(tgemm_k<3>, cudaFuncAttributeMaxDynamicSharedMemorySize, SMEM_DYN);
    cudaFuncSetAttribute(tgemm_k<4>, cudaFuncAttributeMaxDynamicSharedMemorySize, SMEM_DYN);
    cudaFuncSetAttribute(tgemm_k<5>, cudaFuncAttributeMaxDynamicSharedMemorySize, SMEM_DYN);

    zero_k<<<4096, 256>>>();
    agg_k<<<EE * 32 / 256, 256>>>(x, ei);

    // local branch: h1 = (agg/cnt) @ Wc^T + bc + x ; BN1 stats
    tgemm_k<1><<<dim3(NTN / 128, 1), 256, SMEM_DYN>>>(Wc, bc, x);
    ssum_k<<<NTN / 128, 256>>>(0);
    stats_k<<<1, 128>>>(0, gn1, bn1);

    // global branch: qkv projection -> q/k/v in [B*H, N, DH] layout
    tgemm_k<2><<<dim3(NTN / 128, 3), 256, SMEM_DYN>>>(ipw, ipb, x);

    attn_k<<<BG * HH, NNq>>>();

    // h2 = o @ out_proj^T + b + x ; BN2 stats
    tgemm_k<3><<<dim3(NTN / 128, 1), 256, SMEM_DYN>>>(opw, opb, x);
    ssum_k<<<NTN / 128, 256>>>(1);
    stats_k<<<1, 128>>>(1, gn2, bn2);

    // MLP: t = relu(u @ Wm1^T + bm1); f = u + t @ Wm2^T + bm2 ; BN3 stats
    tgemm_k<4><<<dim3(NTN / 128, 2), 256, SMEM_DYN>>>(Wm1, bm1, nullptr);
    tgemm_k<5><<<dim3(NTN / 128, 1), 256, SMEM_DYN>>>(Wm2, bm2, nullptr);
    ssum_k<<<NTN / 128, 256>>>(2);
    stats_k<<<1, 128>>>(2, gn3, bn3);

    bn3_k<<<NTN * CC / 4 / 256, 256>>>(out);
}